// round 4
// baseline (speedup 1.0000x reference)
#include <cuda_runtime.h>
#include <cuda_bf16.h>
#include <cstdint>

// upfirdn2d(x, outer([1,3,3,1])*4/64, up=2, pad=(2,1))
// Per-dim: even out 2i = .75*x[i] + .25*x[i-1]; odd out 2i+1 = .75*x[i] + .25*x[i+1]
//
// One warp per 4 consecutive input rows (8 output rows, 4KB output).
// Loads rows i0-1 .. i0+4 (6 x float2/lane), horizontal-filters each once,
// vertical-blends into 8 output rows (8 x float4/lane, fully coalesced).

static constexpr int H  = 64;
static constexpr int W  = 64;
static constexpr int OW = 128;
static constexpr int RPW = 4;   // input rows per warp

__global__ __launch_bounds__(256) void upsample_fir_quad_kernel(
    const float* __restrict__ x, float* __restrict__ out)
{
    const int gw   = (blockIdx.x << 3) + (threadIdx.x >> 5); // global warp
    const int lane = threadIdx.x & 31;

    const int plane = gw >> 4;              // 16 warps per plane (64/4)
    const int i0    = (gw & 15) * RPW;      // first input row of this warp

    const float* __restrict__ xp = x   + plane * (H * W) + 2 * lane;
    float*       __restrict__ op = out + plane * (2 * H * OW) + (i0 << 8) + 4 * lane;

    // Load 6 input rows: i0-1 .. i0+4 (zero outside [0,H)).
    float2 r[RPW + 2];
    #pragma unroll
    for (int j = 0; j < RPW + 2; j++) {
        const int row = i0 - 1 + j;
        r[j] = ((unsigned)row < (unsigned)H)
                 ? *reinterpret_cast<const float2*>(xp + row * W)
                 : make_float2(0.f, 0.f);
    }

    // Cross-lane neighbors (zero at tile edges = zero padding).
    float rp[RPW + 2], rn[RPW + 2];
    #pragma unroll
    for (int j = 0; j < RPW + 2; j++) {
        rp[j] = __shfl_up_sync(0xffffffffu, r[j].y, 1);
        rn[j] = __shfl_down_sync(0xffffffffu, r[j].x, 1);
    }
    if (lane == 0) {
        #pragma unroll
        for (int j = 0; j < RPW + 2; j++) rp[j] = 0.f;
    }
    if (lane == 31) {
        #pragma unroll
        for (int j = 0; j < RPW + 2; j++) rn[j] = 0.f;
    }

    const float W0 = 0.75f, W1 = 0.25f;

    // Horizontal filter each loaded row once -> 4 output cols per lane.
    float h[RPW + 2][4];
    #pragma unroll
    for (int j = 0; j < RPW + 2; j++) {
        h[j][0] = W0 * r[j].x + W1 * rp[j];
        h[j][1] = W0 * r[j].x + W1 * r[j].y;
        h[j][2] = W0 * r[j].y + W1 * r[j].x;
        h[j][3] = W0 * r[j].y + W1 * rn[j];
    }

    // Vertical blend + store 8 output rows.
    #pragma unroll
    for (int k = 0; k < RPW; k++) {
        float4 e, o;
        e.x = W0 * h[k + 1][0] + W1 * h[k][0];
        e.y = W0 * h[k + 1][1] + W1 * h[k][1];
        e.z = W0 * h[k + 1][2] + W1 * h[k][2];
        e.w = W0 * h[k + 1][3] + W1 * h[k][3];

        o.x = W0 * h[k + 1][0] + W1 * h[k + 2][0];
        o.y = W0 * h[k + 1][1] + W1 * h[k + 2][1];
        o.z = W0 * h[k + 1][2] + W1 * h[k + 2][2];
        o.w = W0 * h[k + 1][3] + W1 * h[k + 2][3];

        *reinterpret_cast<float4*>(op + (2 * k) * OW)     = e;
        *reinterpret_cast<float4*>(op + (2 * k + 1) * OW) = o;
    }
}

extern "C" void kernel_launch(void* const* d_in, const int* in_sizes, int n_in,
                              void* d_out, int out_size)
{
    const float* x = (const float*)d_in[0];
    float* out = (float*)d_out;

    // 16*256 planes, 16 warps per plane (4 input rows each).
    const int n_warps = 16 * 256 * (H / RPW);     // 65536
    const int threads = 256;                      // 8 warps/block
    const int blocks  = n_warps / (threads / 32); // 8192

    upsample_fir_quad_kernel<<<blocks, threads>>>(x, out);
}